// round 2
// baseline (speedup 1.0000x reference)
#include <cuda_runtime.h>
#include <cstddef>

// DerivativeNet forward, direction='x'
// u:    [B=16, C=2, H=1024, W=1024] float32
// mask: [B=16, 1,   H=1024, W=1024] float32 (values exactly 0.0 or 1.0)
// out = eroded*central + edge1*forward + edge2*backward  (zero-padded stencils, h=0.01)

#define WIDTH   1024
#define HEIGHT  1024
#define CHANS   2
#define INV_H   100.0f   // 1/h
#define INV_2H  50.0f    // 1/(2h)
#define NTHREADS 256     // 4 elements per thread

__global__ __launch_bounds__(NTHREADS, 4)
void derivative_net_kernel(const float* __restrict__ u,
                           const float* __restrict__ mask,
                           float* __restrict__ out)
{
    // one block per (b, y) row; both channels share the mask work
    const int row = blockIdx.x;              // b*HEIGHT + y
    const int tid = threadIdx.x;
    const int lane = tid & 31;
    const int wid  = tid >> 5;
    const int i0 = tid * 4;                  // first element index of this thread

    __shared__ float sm[WIDTH + 2];          // mask row, zero halo
    __shared__ float su[WIDTH + 2];          // u row, zero halo
    __shared__ int   pre[WIDTH];             // inclusive prefix of mask bits
    __shared__ int   wsums[8];               // per-warp scan
    __shared__ int   s_total;

    if (tid == 0) {
        sm[0] = 0.0f; sm[WIDTH + 1] = 0.0f;
        su[0] = 0.0f; su[WIDTH + 1] = 0.0f;
    }

    // ---- load mask row (vectorized), stage to shared ----
    const float4 m4 = reinterpret_cast<const float4*>(mask + (size_t)row * WIDTH)[tid];
    sm[i0 + 1] = m4.x; sm[i0 + 2] = m4.y; sm[i0 + 3] = m4.z; sm[i0 + 4] = m4.w;

    const int b0 = (m4.x != 0.0f), b1 = (m4.y != 0.0f),
              b2 = (m4.z != 0.0f), b3 = (m4.w != 0.0f);
    const int tsum = b0 + b1 + b2 + b3;

    // warp-inclusive scan of per-thread counts
    int v = tsum;
    #pragma unroll
    for (int o = 1; o < 32; o <<= 1) {
        int n = __shfl_up_sync(0xffffffffu, v, o);
        if (lane >= o) v += n;
    }
    if (lane == 31) wsums[wid] = v;
    __syncthreads();                          // sm[] + wsums[] visible

    if (tid == 0) {
        int acc = 0;
        #pragma unroll
        for (int w = 0; w < 8; w++) { int x = wsums[w]; wsums[w] = acc; acc += x; }
        s_total = acc;
    }
    __syncthreads();

    const int excl = v - tsum + wsums[wid];   // exclusive prefix at i0
    pre[i0]     = excl + b0;
    pre[i0 + 1] = excl + b0 + b1;
    pre[i0 + 2] = excl + b0 + b1 + b2;
    pre[i0 + 3] = excl + b0 + b1 + b2 + b3;
    const int total = s_total;

    // pre[] entries are only read by the thread that wrote them; sm[] already synced.

    const int b = row / HEIGHT;
    const int y = row - b * HEIGHT;
    const size_t base0 = (((size_t)b * CHANS) * HEIGHT + y) * WIDTH;   // channel 0

    #pragma unroll
    for (int c = 0; c < CHANS; c++) {
        const size_t off = base0 + (size_t)c * (HEIGHT * WIDTH);
        const float4 u4 = reinterpret_cast<const float4*>(u + off)[tid];
        su[i0 + 1] = u4.x; su[i0 + 2] = u4.y; su[i0 + 3] = u4.z; su[i0 + 4] = u4.w;
        __syncthreads();

        float r[4];
        #pragma unroll
        for (int k = 0; k < 4; k++) {
            const int i = i0 + k;
            const float um1 = su[i], ui = su[i + 1], up1 = su[i + 2];
            const float central  = (up1 - um1) * INV_2H;
            const float forward  = (up1 - ui)  * INV_H;
            const float backward = (ui  - um1) * INV_H;

            const bool mcur = (sm[i + 1] != 0.0f);
            const bool er   = (sm[i] != 0.0f) && mcur && (sm[i + 2] != 0.0f);
            const int  p    = pre[i];
            const bool e1   = (p == 1);                // cs == 1 (not masked by m!)
            const bool e2   = mcur && (p == total);    // cs == row_max & m

            r[k] = (er ? central : 0.0f) + (e1 ? forward : 0.0f) + (e2 ? backward : 0.0f);
        }
        reinterpret_cast<float4*>(out + off)[tid] =
            make_float4(r[0], r[1], r[2], r[3]);

        if (c == 0) __syncthreads();          // protect su before reuse
    }
}

extern "C" void kernel_launch(void* const* d_in, const int* in_sizes, int n_in,
                              void* d_out, int out_size)
{
    const float* u    = (const float*)d_in[0];
    const float* mask = (const float*)d_in[1];
    float* out = (float*)d_out;

    const int B = 16;
    const int nrows = B * HEIGHT;             // 16384 blocks
    derivative_net_kernel<<<nrows, NTHREADS>>>(u, mask, out);
}

// round 3
// speedup vs baseline: 1.8068x; 1.8068x over previous
#include <cuda_runtime.h>
#include <cstddef>

// DerivativeNet forward, direction='x'
// u:    [B=16, C=2, H=1024, W=1024] float32
// mask: [B=16, 1,   H=1024, W=1024] float32 (values exactly 0.0 or 1.0)
// out = eroded*central + edge1*forward + edge2*backward (zero-padded stencils, h=0.01)
//
// Register-resident version: each thread owns 4 contiguous elements; halos via
// warp shuffles, warp-boundary halos + scan partials via ~100B of shared.

#define WIDTH   1024
#define HEIGHT  1024
#define INV_H   100.0f
#define INV_2H  50.0f
#define NT      256

__device__ __forceinline__ float delem(float um1, float ui, float up1,
                                       bool er, bool e1, bool e2)
{
    float r = er ? (up1 - um1) * INV_2H : 0.0f;
    r += e1 ? (up1 - ui) * INV_H : 0.0f;
    r += e2 ? (ui - um1) * INV_H : 0.0f;
    return r;
}

__global__ __launch_bounds__(NT, 4)
void dnet_kernel(const float* __restrict__ u,
                 const float* __restrict__ mask,
                 float* __restrict__ out)
{
    const int row  = blockIdx.x;           // b*HEIGHT + y
    const int tid  = threadIdx.x;
    const int lane = tid & 31;
    const int wid  = tid >> 5;

    __shared__ int   wsums[8];
    __shared__ int   em_last[8],  em_first[8];   // mask bits at warp edges
    __shared__ float ea_last[8],  ea_first[8];   // u ch0 at warp edges
    __shared__ float ec_last[8],  ec_first[8];   // u ch1 at warp edges

    const int    b      = row >> 10;
    const int    y      = row & (HEIGHT - 1);
    const size_t ubase0 = (((size_t)(b * 2)) << 20) | ((size_t)y << 10);
    const size_t ubase1 = ubase0 + (size_t)(HEIGHT * WIDTH);

    // ---- issue all three vector loads up front (MLP=3) ----
    const float4 m4 = reinterpret_cast<const float4*>(mask + ((size_t)row << 10))[tid];
    const float4 a4 = reinterpret_cast<const float4*>(u + ubase0)[tid];
    const float4 c4 = reinterpret_cast<const float4*>(u + ubase1)[tid];

    const int b0 = (m4.x != 0.0f), b1 = (m4.y != 0.0f),
              b2 = (m4.z != 0.0f), b3 = (m4.w != 0.0f);
    const int tsum = b0 + b1 + b2 + b3;

    // ---- warp-inclusive scan of per-thread mask counts ----
    int v = tsum;
    #pragma unroll
    for (int o = 1; o < 32; o <<= 1) {
        int n = __shfl_up_sync(0xffffffffu, v, o);
        if (lane >= o) v += n;
    }

    // ---- in-warp halo exchange (registers only) ----
    int   ml = __shfl_up_sync  (0xffffffffu, b3,   1);
    float al = __shfl_up_sync  (0xffffffffu, a4.w, 1);
    float cl = __shfl_up_sync  (0xffffffffu, c4.w, 1);
    int   mr = __shfl_down_sync(0xffffffffu, b0,   1);
    float ar = __shfl_down_sync(0xffffffffu, a4.x, 1);
    float cr = __shfl_down_sync(0xffffffffu, c4.x, 1);

    // ---- cross-warp edges + scan partials through (tiny) shared ----
    if (lane == 31) {
        wsums[wid] = v;
        em_last[wid] = b3; ea_last[wid] = a4.w; ec_last[wid] = c4.w;
    }
    if (lane == 0) {
        em_first[wid] = b0; ea_first[wid] = a4.x; ec_first[wid] = c4.x;
    }
    __syncthreads();

    // each thread computes its warp-exclusive prefix and the row total
    int excl  = v - tsum;
    int total = 0;
    #pragma unroll
    for (int w = 0; w < 8; w++) {
        const int x = wsums[w];               // broadcast LDS, conflict-free
        if (w < wid) excl += x;
        total += x;
    }

    // fix up halos at warp boundaries (zero-padding at row ends)
    if (lane == 0) {
        if (wid > 0) { ml = em_last[wid-1]; al = ea_last[wid-1]; cl = ec_last[wid-1]; }
        else         { ml = 0; al = 0.0f; cl = 0.0f; }
    }
    if (lane == 31) {
        if (wid < 7) { mr = em_first[wid+1]; ar = ea_first[wid+1]; cr = ec_first[wid+1]; }
        else         { mr = 0; ar = 0.0f; cr = 0.0f; }
    }

    // ---- per-element conditions (all in registers) ----
    const int p0 = excl + b0, p1 = p0 + b1, p2 = p1 + b2, p3 = p2 + b3;

    const bool er0 = ml && b0 && b1;
    const bool er1 = b0 && b1 && b2;
    const bool er2 = b1 && b2 && b3;
    const bool er3 = b2 && b3 && mr;

    const bool e10 = (p0 == 1), e11 = (p1 == 1), e12 = (p2 == 1), e13 = (p3 == 1);
    const bool e20 = b0 && (p0 == total);
    const bool e21 = b1 && (p1 == total);
    const bool e22 = b2 && (p2 == total);
    const bool e23 = b3 && (p3 == total);

    // ---- channel 0 ----
    float4 rA;
    rA.x = delem(al,   a4.x, a4.y, er0, e10, e20);
    rA.y = delem(a4.x, a4.y, a4.z, er1, e11, e21);
    rA.z = delem(a4.y, a4.z, a4.w, er2, e12, e22);
    rA.w = delem(a4.z, a4.w, ar,   er3, e13, e23);
    reinterpret_cast<float4*>(out + ubase0)[tid] = rA;

    // ---- channel 1 ----
    float4 rC;
    rC.x = delem(cl,   c4.x, c4.y, er0, e10, e20);
    rC.y = delem(c4.x, c4.y, c4.z, er1, e11, e21);
    rC.z = delem(c4.y, c4.z, c4.w, er2, e12, e22);
    rC.w = delem(c4.z, c4.w, cr,   er3, e13, e23);
    reinterpret_cast<float4*>(out + ubase1)[tid] = rC;
}

extern "C" void kernel_launch(void* const* d_in, const int* in_sizes, int n_in,
                              void* d_out, int out_size)
{
    const float* u    = (const float*)d_in[0];
    const float* mask = (const float*)d_in[1];
    float* o = (float*)d_out;

    const int nrows = 16 * HEIGHT;   // 16384 blocks, one per (b, y) row
    dnet_kernel<<<nrows, NT>>>(u, mask, o);
}